// round 15
// baseline (speedup 1.0000x reference)
#include <cuda_runtime.h>
#include <cstdint>

#define BATCH 8
#define HH 480
#define WW 640
#define PLANE (HH * WW)
#define NPIX (BATCH * PLANE)
#define TFUSE 8

#define TILE 48                   // inner tile 48x48
#define OFF  7                    // inner rows: region rows 7..54
#define ICOL0 8                   // inner cols: region cols 8..55 (groups 2..13)
#define NGRP 16                   // region cols 0..63
#define CROWS 62                  // region rows 0..61
#define BROWS 64                  // feature buffer rows (region rows -1..62)
#define BSTR 72                   // feature buffer cols; ring at cols 3 / 68
#define NTHREADS 992              // 31 warps; warp = 2 rows x 16 groups
#define NF4 (BROWS * (BSTR / 4))  // 1152 float4s per feature buffer
#define GRIDX 14                  // 13 full x-tiles + 1 shifted (ox=592)
#define GRIDY 10

#define AFF_PLANE_F (CROWS * 64)            // 3968 floats per plane
#define AFF_F (8 * AFF_PLANE_F)             // 31744 floats
#define FBUF_F (BROWS * BSTR)               // 4608 floats
#define SMEM_FLOATS (AFF_F + 3 * FBUF_F)    // 45568
#define SMEM_BYTES (SMEM_FLOATS * 4)        // 182272

// Scratch (allocation-free rule: __device__ globals)
__device__ float g_buf0[NPIX];
__device__ float g_buf1[NPIX];

__device__ __forceinline__ void cp16(unsigned int dst_smem, const float* src, bool ok) {
    const int sz = ok ? 16 : 0;
    asm volatile("cp.async.cg.shared.global [%0], [%1], 16, %2;\n"
                 :: "r"(dst_smem), "l"(src), "r"(sz));
}
__device__ __forceinline__ void cp_commit() {
    asm volatile("cp.async.commit_group;\n" ::: "memory");
}
__device__ __forceinline__ void cp_wait0() {
    asm volatile("cp.async.wait_group 0;\n" ::: "memory");
}

// ---------------------------------------------------------------------------
// Persistent-over-batch fused kernel.
// Per batch: weights(b) normalized from smem-staged affinity into registers,
// cp.async prefetch of affinity(b+1) + feature-window(b+1) overlaps the
// TFUSE-iteration propagation loop.
// ---------------------------------------------------------------------------
__global__ void __launch_bounds__(NTHREADS, 1)
fused_kernel(const float* __restrict__ affinity,
             const float* __restrict__ fin, float* __restrict__ fout) {
    extern __shared__ __align__(16) float smem[];
    float* aff_s = smem;

    const int tid  = threadIdx.x;
    const int lane = tid & 31;
    const int grp  = lane & 15;                       // col group 0..15
    const int row  = ((tid >> 5) << 1) + (lane >> 4); // region row 0..61
    const int ox = (blockIdx.x < GRIDX - 1) ? blockIdx.x * TILE : (WW - TILE);
    const int oy = blockIdx.y * TILE;

    const unsigned int aff_u32 = (unsigned int)__cvta_generic_to_shared(aff_s);

    // ---- writer mapping for affinity staging (coalesced) ----
    const int wrow  = tid >> 4;            // 0..61
    const int wcol4 = tid & 15;            // 0..15
    const int agy = oy - OFF + wrow;
    const int agx = ox - ICOL0 + wcol4 * 4;
    const bool aok = (agy >= 0 && agy < HH && agx >= 0 && agx < WW);
    const size_t aoff = aok ? ((size_t)agy * WW + agx) : 0;
    const unsigned int adst0 = aff_u32 + (unsigned int)(wrow * 64 + wcol4 * 4) * 4u;

    // ---- per-thread compute-region identity ----
    const int gy  = oy - OFF + row;
    const int gx0 = ox - ICOL0 + grp * 4;
    const bool ok = (gy >= 0 && gy < HH && gx0 >= 0 && gx0 < WW);

    // ---- prologue: prefetch batch 0 ----
    {
        const float* ab = affinity + aoff;
#pragma unroll
        for (int c = 0; c < 8; c++)
            cp16(adst0 + (unsigned int)(c * AFF_PLANE_F) * 4u, ab + (size_t)c * PLANE, aok);
#pragma unroll
        for (int r = 0; r < 2; r++) {
            const int idx = tid + r * NTHREADS;
            if (idx < NF4) {
                const int fr = idx / 18, fc4 = idx % 18;
                const int gyw = oy - 8 + fr, gxw = ox - 12 + fc4 * 4;
                const bool fok = (gyw >= 0 && gyw < HH && gxw >= 0 && gxw < WW);
                const float* src = fin + (fok ? ((size_t)gyw * WW + gxw) : 0);
                unsigned int dst = (unsigned int)__cvta_generic_to_shared(
                    smem + AFF_F + fr * BSTR + fc4 * 4);
                cp16(dst, src, fok);
            }
        }
        cp_commit();
    }

    const float4 z4 = make_float4(0.f, 0.f, 0.f, 0.f);

    for (int b = 0; b < BATCH; b++) {
        float* P = smem + AFF_F + (b % 3) * FBUF_F;        // prefetched window
        float* S = smem + AFF_F + ((b + 2) % 3) * FBUF_F;  // scratch ping-pong
        float* F = smem + AFF_F + ((b + 1) % 3) * FBUF_F;  // next prefetch tgt

        cp_wait0();
        __syncthreads();

        // ---- normalize weights(b) from staged affinity ----
        float4 w4[9];
        {
            float4 a[8];
            float4 s = z4;
#pragma unroll
            for (int c = 0; c < 8; c++) {
                a[c] = *(const float4*)(aff_s + c * AFF_PLANE_F + row * 64 + grp * 4);
                s.x += fabsf(a[c].x); s.y += fabsf(a[c].y);
                s.z += fabsf(a[c].z); s.w += fabsf(a[c].w);
            }
            const float4 inv = ok ? make_float4(1.f/s.x, 1.f/s.y, 1.f/s.z, 1.f/s.w) : z4;
            float4 ns = z4;
#pragma unroll
            for (int c = 0; c < 8; c++) {
                a[c].x *= inv.x; a[c].y *= inv.y;
                a[c].z *= inv.z; a[c].w *= inv.w;
                ns.x += a[c].x; ns.y += a[c].y;
                ns.z += a[c].z; ns.w += a[c].w;
            }
#pragma unroll
            for (int c = 0; c < 4; c++) w4[c] = a[c];
            w4[4] = ok ? make_float4(1.f - ns.x, 1.f - ns.y, 1.f - ns.z, 1.f - ns.w) : z4;
#pragma unroll
            for (int c = 4; c < 8; c++) w4[c + 1] = a[c];
        }
        __syncthreads();   // all aff_s reads done before refill

        // ---- prefetch batch b+1 (overlaps the loop below) ----
        if (b < BATCH - 1) {
            const float* ab = affinity + (size_t)(b + 1) * 8 * PLANE + aoff;
#pragma unroll
            for (int c = 0; c < 8; c++)
                cp16(adst0 + (unsigned int)(c * AFF_PLANE_F) * 4u, ab + (size_t)c * PLANE, aok);
            const float* fsrc = fin + (size_t)(b + 1) * PLANE;
#pragma unroll
            for (int r = 0; r < 2; r++) {
                const int idx = tid + r * NTHREADS;
                if (idx < NF4) {
                    const int fr = idx / 18, fc4 = idx % 18;
                    const int gyw = oy - 8 + fr, gxw = ox - 12 + fc4 * 4;
                    const bool fok = (gyw >= 0 && gyw < HH && gxw >= 0 && gxw < WW);
                    const float* src = fsrc + (fok ? ((size_t)gyw * WW + gxw) : 0);
                    unsigned int dst = (unsigned int)__cvta_generic_to_shared(
                        F + fr * BSTR + fc4 * 4);
                    cp16(dst, src, fok);
                }
            }
            cp_commit();
        }

        // ---- copy static ring P -> S (interior of S overwritten at t=0) ----
#pragma unroll
        for (int r = 0; r < 2; r++) {
            const int idx = tid + r * NTHREADS;
            if (idx < NF4) {
                const int br = idx / 18, bc4 = idx % 18;
                if (br == 0 || br == BROWS - 1 || bc4 == 0 || bc4 == 17)
                    ((float4*)(S + br * BSTR))[bc4] = ((const float4*)(P + br * BSTR))[bc4];
            }
        }

        // ---- hoist static ring columns ----
        const bool isL = (grp == 0), isR = (grp == 15);
        float ringL[3] = {0.f, 0.f, 0.f}, ringR[3] = {0.f, 0.f, 0.f};
        if (isL) {
#pragma unroll
            for (int r = 0; r < 3; r++) ringL[r] = P[(row + r) * BSTR + 3];
        }
        if (isR) {
#pragma unroll
            for (int r = 0; r < 3; r++) ringR[r] = P[(row + r) * BSTR + 68];
        }

        // ---- TFUSE fused iterations ----
        const int bcol = grp * 4 + 4;
        float c0 = 0.f, c1 = 0.f, c2 = 0.f, c3 = 0.f;
        float a0, a1, a2, a3;
        const float* bufs[2] = { P, S };
        int cur = 0;
#pragma unroll
        for (int t = 0; t < TFUSE; t++) {
            const float* s = bufs[cur];
            const float4 r0 = *(const float4*)(s + row * BSTR + bcol);
            float4 r1;
            if (t == 0) r1 = *(const float4*)(s + (row + 1) * BSTR + bcol);
            else        r1 = make_float4(c0, c1, c2, c3);
            const float4 r2 = *(const float4*)(s + (row + 2) * BSTR + bcol);

            a0 = a1 = a2 = a3 = 0.f;
#pragma unroll
            for (int rr = 0; rr < 3; rr++) {
                const float4 rv = (rr == 0) ? r0 : (rr == 1) ? r1 : r2;
                float f0 = __shfl_up_sync(0xffffffffu, rv.w, 1);
                float f5 = __shfl_down_sync(0xffffffffu, rv.x, 1);
                if (isL) f0 = ringL[rr];
                if (isR) f5 = ringR[rr];
                const float4 wa = w4[3 * rr + 0];
                const float4 wb = w4[3 * rr + 1];
                const float4 wc = w4[3 * rr + 2];
                a0 = fmaf(wa.x, f0,   fmaf(wb.x, rv.x, fmaf(wc.x, rv.y, a0)));
                a1 = fmaf(wa.y, rv.x, fmaf(wb.y, rv.y, fmaf(wc.y, rv.z, a1)));
                a2 = fmaf(wa.z, rv.y, fmaf(wb.z, rv.z, fmaf(wc.z, rv.w, a2)));
                a3 = fmaf(wa.w, rv.z, fmaf(wb.w, rv.w, fmaf(wc.w, f5,   a3)));
            }
            c0 = a0; c1 = a1; c2 = a2; c3 = a3;
            if (t < TFUSE - 1) {
                *(float4*)((float*)bufs[cur ^ 1] + (row + 1) * BSTR + bcol) =
                    make_float4(a0, a1, a2, a3);
                __syncthreads();
            }
            cur ^= 1;
        }

        // ---- write inner 48x48 from registers ----
        if (row >= OFF && row < OFF + TILE && grp >= 2 && grp < 14) {
            float* out = fout + (size_t)b * PLANE;
            *(float4*)(out + gy * WW + gx0) = make_float4(c0, c1, c2, c3);
        }
        __syncthreads();   // t=7 reads of P/S done before next batch reuses them
    }
}

// ---------------------------------------------------------------------------
extern "C" void kernel_launch(void* const* d_in, const int* in_sizes, int n_in,
                              void* d_out, int out_size) {
    const float* affinity = (const float*)d_in[0];
    const float* feature  = (const float*)d_in[1];
    float* out = (float*)d_out;

    cudaFuncSetAttribute(fused_kernel,
                         cudaFuncAttributeMaxDynamicSharedMemorySize, SMEM_BYTES);

    void* p0 = nullptr; void* p1 = nullptr;
    cudaGetSymbolAddress(&p0, g_buf0);
    cudaGetSymbolAddress(&p1, g_buf1);

    dim3 grd(GRIDX, GRIDY, 1);   // 140 CTAs, persistent over batch
    fused_kernel<<<grd, NTHREADS, SMEM_BYTES>>>(affinity, feature, (float*)p0);
    fused_kernel<<<grd, NTHREADS, SMEM_BYTES>>>(affinity, (float*)p0, (float*)p1);
    fused_kernel<<<grd, NTHREADS, SMEM_BYTES>>>(affinity, (float*)p1, out);
    (void)in_sizes; (void)n_in; (void)out_size;
}